// round 12
// baseline (speedup 1.0000x reference)
#include <cuda_runtime.h>
#include <cuda_bf16.h>
#include <cstdint>

// ---------------------------------------------------------------------------
// ExpertSelector: dynamic-k MoE router
//   logits = X @ Wr^T + br            [N, 64]   (fp32 reverse-k — FROZEN bits)
//   h      = relu(X @ W1^T + b1)      [N, 512]  (fp32 — FROZEN bits)
//   conf/dk: fp32 round-1 form (dk-validated on these g_h bits)
//   top-8: sort by FROZEN logit bits; values fp32 softmax. NO fp64.
// Output (float32 concat): sel_w [N*8] | sel_i [N*8] | conf [N] | logits [N*64]
//
// GEMM: 8x8 outer-product per thread, k-major smem, reg-staged double buffer.
// Per-output FMA chains identical to round-11 passing kernel (h: ascending
// tiles+kk; router: reversed tiles, ascending kk) -> all bits preserved.
// ---------------------------------------------------------------------------

#define BM 128
#define BN 64
#define BK 32
#define THREADS 128

// scratch for relu(h): 32768 x 512 floats = 64 MB
__device__ float g_h[32768ull * 512ull];

__global__ __launch_bounds__(THREADS, 3) void es_gemm_fused_kernel(
    const float* __restrict__ X,
    const float* __restrict__ Wr, const float* __restrict__ br,
    const float* __restrict__ W1, const float* __restrict__ b1,
    float* __restrict__ logits_out,
    int N, int H, int E, int Hh)
{
    __shared__ float Xs[2][BK][BM];   // k-major: [k][row]
    __shared__ float Ws[2][BK][BN];   // k-major: [k][col]

    const int t   = threadIdx.x;
    const int tx2 = t & 7;            // col block: cols tx2*8 .. +7
    const int ty2 = t >> 3;           // row block: rows ty2*8 .. +7
    const int row0 = blockIdx.x * BM;
    const bool is_router = (blockIdx.y == 8);

    const float* wptr = is_router ? Wr : (W1 + (size_t)blockIdx.y * BN * H);

    // load indices
    const int wc = t & 63;            // W column (2 threads per col)
    const int wh = t >> 6;            // k half: 0 -> k 0..15, 1 -> k 16..31

    float acc[8][8];
#pragma unroll
    for (int i = 0; i < 8; i++)
#pragma unroll
        for (int j = 0; j < 8; j++) acc[i][j] = 0.0f;

    const int T = H / BK;             // 32 tiles

    float4 xr[8], wr[4];

    // ---- prologue: tile 0 (h: k0=0; router: k0=H-BK — reversed order) ----
    {
        const int k0 = is_router ? (H - BK) : 0;
        const float* gx = X + (size_t)(row0 + t) * H + k0;
#pragma unroll
        for (int i = 0; i < 8; i++) xr[i] = *(const float4*)(gx + i * 4);
        const float* gw = wptr + (size_t)wc * H + k0 + wh * 16;
#pragma unroll
        for (int i = 0; i < 4; i++) wr[i] = *(const float4*)(gw + i * 4);
#pragma unroll
        for (int i = 0; i < 8; i++) {
            Xs[0][i * 4 + 0][t] = xr[i].x;
            Xs[0][i * 4 + 1][t] = xr[i].y;
            Xs[0][i * 4 + 2][t] = xr[i].z;
            Xs[0][i * 4 + 3][t] = xr[i].w;
        }
#pragma unroll
        for (int i = 0; i < 4; i++) {
            Ws[0][wh * 16 + i * 4 + 0][wc] = wr[i].x;
            Ws[0][wh * 16 + i * 4 + 1][wc] = wr[i].y;
            Ws[0][wh * 16 + i * 4 + 2][wc] = wr[i].z;
            Ws[0][wh * 16 + i * 4 + 3][wc] = wr[i].w;
        }
    }
    __syncthreads();

    for (int tt = 0; tt < T; tt++) {
        const int cur = tt & 1;
        const int nxt = cur ^ 1;
        const bool has_next = (tt + 1 < T);

        if (has_next) {
            const int k0 = is_router ? (H - BK - (tt + 1) * BK) : ((tt + 1) * BK);
            const float* gx = X + (size_t)(row0 + t) * H + k0;
#pragma unroll
            for (int i = 0; i < 8; i++) xr[i] = *(const float4*)(gx + i * 4);
            const float* gw = wptr + (size_t)wc * H + k0 + wh * 16;
#pragma unroll
            for (int i = 0; i < 4; i++) wr[i] = *(const float4*)(gw + i * 4);
        }

        // ---- compute tile: kk ascending (order-preserving per output) ----
#pragma unroll
        for (int kk = 0; kk < BK; kk++) {
            float4 xv0 = *(const float4*)&Xs[cur][kk][ty2 * 8];
            float4 xv1 = *(const float4*)&Xs[cur][kk][ty2 * 8 + 4];
            float4 wv0 = *(const float4*)&Ws[cur][kk][tx2 * 8];
            float4 wv1 = *(const float4*)&Ws[cur][kk][tx2 * 8 + 4];
            float xv[8] = {xv0.x, xv0.y, xv0.z, xv0.w, xv1.x, xv1.y, xv1.z, xv1.w};
            float wv[8] = {wv0.x, wv0.y, wv0.z, wv0.w, wv1.x, wv1.y, wv1.z, wv1.w};
#pragma unroll
            for (int i = 0; i < 8; i++)
#pragma unroll
                for (int j = 0; j < 8; j++)
                    acc[i][j] = fmaf(xv[i], wv[j], acc[i][j]);
        }

        if (has_next) {
#pragma unroll
            for (int i = 0; i < 8; i++) {
                Xs[nxt][i * 4 + 0][t] = xr[i].x;
                Xs[nxt][i * 4 + 1][t] = xr[i].y;
                Xs[nxt][i * 4 + 2][t] = xr[i].z;
                Xs[nxt][i * 4 + 3][t] = xr[i].w;
            }
#pragma unroll
            for (int i = 0; i < 4; i++) {
                Ws[nxt][wh * 16 + i * 4 + 0][wc] = wr[i].x;
                Ws[nxt][wh * 16 + i * 4 + 1][wc] = wr[i].y;
                Ws[nxt][wh * 16 + i * 4 + 2][wc] = wr[i].z;
                Ws[nxt][wh * 16 + i * 4 + 3][wc] = wr[i].w;
            }
        }
        __syncthreads();
    }

    // ---- epilogues (same per-element expressions as frozen kernel) ----
    if (is_router) {
#pragma unroll
        for (int i = 0; i < 8; i++) {
            int row = row0 + ty2 * 8 + i;
            if (row >= N) continue;
            float4 a, b;
            a.x = __fadd_rn(acc[i][0], br[tx2 * 8 + 0]);
            a.y = __fadd_rn(acc[i][1], br[tx2 * 8 + 1]);
            a.z = __fadd_rn(acc[i][2], br[tx2 * 8 + 2]);
            a.w = __fadd_rn(acc[i][3], br[tx2 * 8 + 3]);
            b.x = __fadd_rn(acc[i][4], br[tx2 * 8 + 4]);
            b.y = __fadd_rn(acc[i][5], br[tx2 * 8 + 5]);
            b.z = __fadd_rn(acc[i][6], br[tx2 * 8 + 6]);
            b.w = __fadd_rn(acc[i][7], br[tx2 * 8 + 7]);
            *(float4*)&logits_out[(size_t)row * E + tx2 * 8]     = a;
            *(float4*)&logits_out[(size_t)row * E + tx2 * 8 + 4] = b;
        }
    } else {
        const float* bptr = b1 + (size_t)blockIdx.y * BN;
        const int colBase = blockIdx.y * BN;
        float bias[8];
#pragma unroll
        for (int j = 0; j < 8; j++) bias[j] = bptr[tx2 * 8 + j];
#pragma unroll
        for (int i = 0; i < 8; i++) {
            int row = row0 + ty2 * 8 + i;
            if (row >= N) continue;
            float4 a, b;
            a.x = fmaxf(acc[i][0] + bias[0], 0.0f);
            a.y = fmaxf(acc[i][1] + bias[1], 0.0f);
            a.z = fmaxf(acc[i][2] + bias[2], 0.0f);
            a.w = fmaxf(acc[i][3] + bias[3], 0.0f);
            b.x = fmaxf(acc[i][4] + bias[4], 0.0f);
            b.y = fmaxf(acc[i][5] + bias[5], 0.0f);
            b.z = fmaxf(acc[i][6] + bias[6], 0.0f);
            b.w = fmaxf(acc[i][7] + bias[7], 0.0f);
            *(float4*)&g_h[(size_t)row * Hh + colBase + tx2 * 8]     = a;
            *(float4*)&g_h[(size_t)row * Hh + colBase + tx2 * 8 + 4] = b;
        }
    }
}

// ---------------------------------------------------------------------------
// Select: one warp per token. ALL fp32.  *** FROZEN (round-11 body) ***
// ---------------------------------------------------------------------------
__global__ __launch_bounds__(256) void es_select_kernel(
    const float* __restrict__ logits,
    const float* __restrict__ W2, const float* __restrict__ b2,
    float* __restrict__ sel_w, float* __restrict__ sel_i,
    float* __restrict__ conf_out,
    int N, int E, int Hh)
{
    const int gwarp = (blockIdx.x * blockDim.x + threadIdx.x) >> 5;
    const int lane  = threadIdx.x & 31;
    if (gwarp >= N) return;
    const unsigned FULL = 0xFFFFFFFFu;

    const float* L = logits + (size_t)gwarp * E;
    float l0 = L[lane];
    float l1 = L[lane + 32];

    // --- fp32 softmax (VALUES only; order comes from logit bits) ---
    float m = fmaxf(l0, l1);
#pragma unroll
    for (int o = 16; o; o >>= 1) m = fmaxf(m, __shfl_xor_sync(FULL, m, o));
    float e0 = expf(l0 - m);
    float e1 = expf(l1 - m);
    float s = e0 + e1;
#pragma unroll
    for (int o = 16; o; o >>= 1) s += __shfl_xor_sync(FULL, s, o);
    float inv = 1.0f / s;
    float p0 = e0 * inv;
    float p1 = e1 * inv;

    // --- confidence: round-1 fp32 code VERBATIM (dk-validated realization) --
    const float* hr = g_h + (size_t)gwarp * Hh;
    float a = 0.0f;
    for (int i = lane; i < Hh; i += 32) a = fmaf(hr[i], W2[i], a);
#pragma unroll
    for (int o = 16; o; o >>= 1) a += __shfl_xor_sync(FULL, a, o);
    float conf = 1.0f / (1.0f + expf(-(a + b2[0])));
    float dkf = rintf(1.0f + 7.0f * (1.0f - conf));
    int dk = (int)fminf(fmaxf(dkf, 1.0f), 8.0f);
    if (lane == 0) conf_out[gwarp] = conf;

    // --- top-8 via bitonic sort of 64 keys built from LOGIT bits ---
    unsigned ub0 = __float_as_uint(l0);
    unsigned ub1 = __float_as_uint(l1);
    ub0 = (ub0 & 0x80000000u) ? ~ub0 : (ub0 | 0x80000000u);
    ub1 = (ub1 & 0x80000000u) ? ~ub1 : (ub1 | 0x80000000u);
    unsigned long long key0 =
        ((unsigned long long)ub0 << 6) | (unsigned long long)(63 - lane);
    unsigned long long key1 =
        ((unsigned long long)ub1 << 6) | (unsigned long long)(63 - (lane + 32));

    // descending bitonic sort; positions: key0 -> lane, key1 -> lane+32
#pragma unroll
    for (int k = 2; k <= 64; k <<= 1) {
#pragma unroll
        for (int j = k >> 1; j > 0; j >>= 1) {
            if (j == 32) {
                unsigned long long mx = key0 > key1 ? key0 : key1;
                unsigned long long mn = key0 > key1 ? key1 : key0;
                key0 = mx; key1 = mn;
            } else {
                bool wml0 = (k == 64) ? true : ((lane & k) == 0);
                bool wml1 = (k == 64) ? true : (((lane + 32) & k) == 0);
                bool lower = (lane & j) == 0;
                unsigned long long o0 = __shfl_xor_sync(FULL, key0, j);
                unsigned long long o1 = __shfl_xor_sync(FULL, key1, j);
                bool tm0 = (lower == wml0);
                bool tm1 = (lower == wml1);
                key0 = tm0 ? (key0 > o0 ? key0 : o0) : (key0 < o0 ? key0 : o0);
                key1 = tm1 ? (key1 > o1 ? key1 : o1) : (key1 < o1 ? key1 : o1);
            }
        }
    }

    int idx_sel = 63 - (int)(key0 & 63ull);
    float pa = __shfl_sync(FULL, p0, idx_sel & 31);
    float pb = __shfl_sync(FULL, p1, idx_sel & 31);
    float pv = (idx_sel < 32) ? pa : pb;

    if (lane < 8) {
        bool act = lane < dk;
        sel_w[(size_t)gwarp * 8 + lane] = act ? pv : 0.0f;
        sel_i[(size_t)gwarp * 8 + lane] = act ? (float)idx_sel : 0.0f;
    }
}

extern "C" void kernel_launch(void* const* d_in, const int* in_sizes, int n_in,
                              void* d_out, int out_size)
{
    const float* X  = (const float*)d_in[0];
    const float* Wr = (const float*)d_in[1];
    const float* br = (const float*)d_in[2];
    const float* W1 = (const float*)d_in[3];
    const float* b1 = (const float*)d_in[4];
    const float* W2 = (const float*)d_in[5];
    const float* b2 = (const float*)d_in[6];

    const int E  = in_sizes[2];                      // 64
    const int Hh = in_sizes[4];                      // 512
    const int H  = in_sizes[1] / E;                  // 1024
    const long long N = (long long)in_sizes[0] / H;  // 32768

    float* out    = (float*)d_out;
    float* sel_w  = out;
    float* sel_i  = out + N * 8;
    float* conf   = out + 2 * N * 8;
    float* logits = out + 2 * N * 8 + N;

    dim3 ggrid((unsigned)((N + BM - 1) / BM), (unsigned)(Hh / BN) + 1);
    es_gemm_fused_kernel<<<ggrid, THREADS>>>(X, Wr, br, W1, b1, logits,
                                             (int)N, H, E, Hh);

    int warps_per_block = 256 / 32;
    unsigned sel_blocks = (unsigned)((N + warps_per_block - 1) / warps_per_block);
    es_select_kernel<<<sel_blocks, 256>>>(logits, W2, b2,
                                          sel_w, sel_i, conf,
                                          (int)N, E, Hh);
}

// round 13
// speedup vs baseline: 1.3351x; 1.3351x over previous
#include <cuda_runtime.h>
#include <cuda_bf16.h>
#include <cstdint>

// ---------------------------------------------------------------------------
// ExpertSelector: dynamic-k MoE router
//   logits = X @ Wr^T + br            [N, 64]   (fp32 reverse-k — FROZEN bits)
//   h      = relu(X @ W1^T + b1)      [N, 512]  (fp32 — FROZEN bits)
//   conf/dk: fp32 round-1 form (dk-validated on these g_h bits)
//   top-8: sort by FROZEN logit bits; values fp32 softmax. NO fp64.
// Output (float32 concat): sel_w [N*8] | sel_i [N*8] | conf [N] | logits [N*64]
//
// GEMM: 256 threads, tile 256x64, BK=16, 8x8 outer product per thread,
// k-major smem (+4 pad), register staging capped at 20 regs, 2 CTAs/SM.
// Per-output FMA chains preserved exactly:
//   h: k ascending 0..1023 (ascending 16-tiles)
//   router: frozen 32-block-descending order via pair map
//           b = 31-(tt>>1), k0 = b*32 + (tt&1)*16
// ---------------------------------------------------------------------------

#define BM 256
#define BN 64
#define BK 16
#define THREADS 256

// scratch for relu(h): 32768 x 512 floats = 64 MB
__device__ float g_h[32768ull * 512ull];

__global__ __launch_bounds__(THREADS, 2) void es_gemm_fused_kernel(
    const float* __restrict__ X,
    const float* __restrict__ Wr, const float* __restrict__ br,
    const float* __restrict__ W1, const float* __restrict__ b1,
    float* __restrict__ logits_out,
    int N, int H, int E, int Hh)
{
    __shared__ __align__(16) float Xs[2][BK][BM + 4];   // k-major [k][row]
    __shared__ __align__(16) float Ws[2][BK][BN + 4];   // k-major [k][col]

    const int t    = threadIdx.x;
    const int tx2  = t & 7;           // col block: cols tx2*8 .. +7
    const int ty2  = t >> 3;          // row block: rows ty2*8 .. +7 (0..31)
    const int row0 = blockIdx.x * BM;
    const bool is_router = (blockIdx.y == 8);

    const float* wptr = is_router ? Wr : (W1 + (size_t)blockIdx.y * BN * H);

    // staging indices
    const int sr   = t >> 2;          // 0..63 (X row group / W col)
    const int kseg = (t & 3) * 4;     // k offset 0,4,8,12

    float acc[8][8];
#pragma unroll
    for (int i = 0; i < 8; i++)
#pragma unroll
        for (int j = 0; j < 8; j++) acc[i][j] = 0.0f;

    const int T = H / BK;             // 64 tiles

    // k0 for tile index tt (preserves frozen k order for both paths)
    auto tile_k0 = [&](int tt) -> int {
        if (is_router) {
            int b = 31 - (tt >> 1);
            return b * 32 + (tt & 1) * 16;
        }
        return tt * BK;
    };

    float4 xr4[4];
    float4 wr4;

    // ---- prologue: stage tile 0 ----
    {
        const int k0 = tile_k0(0);
#pragma unroll
        for (int i = 0; i < 4; i++)
            xr4[i] = *(const float4*)&X[(size_t)(row0 + i * 64 + sr) * H + k0 + kseg];
        wr4 = *(const float4*)&wptr[(size_t)sr * H + k0 + kseg];
#pragma unroll
        for (int i = 0; i < 4; i++) {
            Xs[0][kseg + 0][i * 64 + sr] = xr4[i].x;
            Xs[0][kseg + 1][i * 64 + sr] = xr4[i].y;
            Xs[0][kseg + 2][i * 64 + sr] = xr4[i].z;
            Xs[0][kseg + 3][i * 64 + sr] = xr4[i].w;
        }
        Ws[0][kseg + 0][sr] = wr4.x;
        Ws[0][kseg + 1][sr] = wr4.y;
        Ws[0][kseg + 2][sr] = wr4.z;
        Ws[0][kseg + 3][sr] = wr4.w;
    }
    __syncthreads();

    for (int tt = 0; tt < T; tt++) {
        const int cur = tt & 1;
        const int nxt = cur ^ 1;
        const bool has_next = (tt + 1 < T);

        if (has_next) {
            const int k0 = tile_k0(tt + 1);
#pragma unroll
            for (int i = 0; i < 4; i++)
                xr4[i] = *(const float4*)&X[(size_t)(row0 + i * 64 + sr) * H + k0 + kseg];
            wr4 = *(const float4*)&wptr[(size_t)sr * H + k0 + kseg];
        }

        // ---- compute tile: kk ascending (order-preserving per output) ----
#pragma unroll
        for (int kk = 0; kk < BK; kk++) {
            float4 xv0 = *(const float4*)&Xs[cur][kk][ty2 * 8];
            float4 xv1 = *(const float4*)&Xs[cur][kk][ty2 * 8 + 4];
            float4 wv0 = *(const float4*)&Ws[cur][kk][tx2 * 8];
            float4 wv1 = *(const float4*)&Ws[cur][kk][tx2 * 8 + 4];
            float xv[8] = {xv0.x, xv0.y, xv0.z, xv0.w, xv1.x, xv1.y, xv1.z, xv1.w};
            float wv[8] = {wv0.x, wv0.y, wv0.z, wv0.w, wv1.x, wv1.y, wv1.z, wv1.w};
#pragma unroll
            for (int i = 0; i < 8; i++)
#pragma unroll
                for (int j = 0; j < 8; j++)
                    acc[i][j] = fmaf(xv[i], wv[j], acc[i][j]);
        }

        if (has_next) {
#pragma unroll
            for (int i = 0; i < 4; i++) {
                Xs[nxt][kseg + 0][i * 64 + sr] = xr4[i].x;
                Xs[nxt][kseg + 1][i * 64 + sr] = xr4[i].y;
                Xs[nxt][kseg + 2][i * 64 + sr] = xr4[i].z;
                Xs[nxt][kseg + 3][i * 64 + sr] = xr4[i].w;
            }
            Ws[nxt][kseg + 0][sr] = wr4.x;
            Ws[nxt][kseg + 1][sr] = wr4.y;
            Ws[nxt][kseg + 2][sr] = wr4.z;
            Ws[nxt][kseg + 3][sr] = wr4.w;
        }
        __syncthreads();
    }

    // ---- epilogues (same per-element expressions as frozen kernel) ----
    if (is_router) {
#pragma unroll
        for (int i = 0; i < 8; i++) {
            int row = row0 + ty2 * 8 + i;
            if (row >= N) continue;
            float4 a, b;
            a.x = __fadd_rn(acc[i][0], br[tx2 * 8 + 0]);
            a.y = __fadd_rn(acc[i][1], br[tx2 * 8 + 1]);
            a.z = __fadd_rn(acc[i][2], br[tx2 * 8 + 2]);
            a.w = __fadd_rn(acc[i][3], br[tx2 * 8 + 3]);
            b.x = __fadd_rn(acc[i][4], br[tx2 * 8 + 4]);
            b.y = __fadd_rn(acc[i][5], br[tx2 * 8 + 5]);
            b.z = __fadd_rn(acc[i][6], br[tx2 * 8 + 6]);
            b.w = __fadd_rn(acc[i][7], br[tx2 * 8 + 7]);
            *(float4*)&logits_out[(size_t)row * E + tx2 * 8]     = a;
            *(float4*)&logits_out[(size_t)row * E + tx2 * 8 + 4] = b;
        }
    } else {
        const float* bptr = b1 + (size_t)blockIdx.y * BN;
        const int colBase = blockIdx.y * BN;
        float bias[8];
#pragma unroll
        for (int j = 0; j < 8; j++) bias[j] = bptr[tx2 * 8 + j];
#pragma unroll
        for (int i = 0; i < 8; i++) {
            int row = row0 + ty2 * 8 + i;
            if (row >= N) continue;
            float4 a, b;
            a.x = fmaxf(acc[i][0] + bias[0], 0.0f);
            a.y = fmaxf(acc[i][1] + bias[1], 0.0f);
            a.z = fmaxf(acc[i][2] + bias[2], 0.0f);
            a.w = fmaxf(acc[i][3] + bias[3], 0.0f);
            b.x = fmaxf(acc[i][4] + bias[4], 0.0f);
            b.y = fmaxf(acc[i][5] + bias[5], 0.0f);
            b.z = fmaxf(acc[i][6] + bias[6], 0.0f);
            b.w = fmaxf(acc[i][7] + bias[7], 0.0f);
            *(float4*)&g_h[(size_t)row * Hh + colBase + tx2 * 8]     = a;
            *(float4*)&g_h[(size_t)row * Hh + colBase + tx2 * 8 + 4] = b;
        }
    }
}

// ---------------------------------------------------------------------------
// Select: one warp per token. ALL fp32.  *** FROZEN (round-11 body) ***
// ---------------------------------------------------------------------------
__global__ __launch_bounds__(256) void es_select_kernel(
    const float* __restrict__ logits,
    const float* __restrict__ W2, const float* __restrict__ b2,
    float* __restrict__ sel_w, float* __restrict__ sel_i,
    float* __restrict__ conf_out,
    int N, int E, int Hh)
{
    const int gwarp = (blockIdx.x * blockDim.x + threadIdx.x) >> 5;
    const int lane  = threadIdx.x & 31;
    if (gwarp >= N) return;
    const unsigned FULL = 0xFFFFFFFFu;

    const float* L = logits + (size_t)gwarp * E;
    float l0 = L[lane];
    float l1 = L[lane + 32];

    // --- fp32 softmax (VALUES only; order comes from logit bits) ---
    float m = fmaxf(l0, l1);
#pragma unroll
    for (int o = 16; o; o >>= 1) m = fmaxf(m, __shfl_xor_sync(FULL, m, o));
    float e0 = expf(l0 - m);
    float e1 = expf(l1 - m);
    float s = e0 + e1;
#pragma unroll
    for (int o = 16; o; o >>= 1) s += __shfl_xor_sync(FULL, s, o);
    float inv = 1.0f / s;
    float p0 = e0 * inv;
    float p1 = e1 * inv;

    // --- confidence: round-1 fp32 code VERBATIM (dk-validated realization) --
    const float* hr = g_h + (size_t)gwarp * Hh;
    float a = 0.0f;
    for (int i = lane; i < Hh; i += 32) a = fmaf(hr[i], W2[i], a);
#pragma unroll
    for (int o = 16; o; o >>= 1) a += __shfl_xor_sync(FULL, a, o);
    float conf = 1.0f / (1.0f + expf(-(a + b2[0])));
    float dkf = rintf(1.0f + 7.0f * (1.0f - conf));
    int dk = (int)fminf(fmaxf(dkf, 1.0f), 8.0f);
    if (lane == 0) conf_out[gwarp] = conf;

    // --- top-8 via bitonic sort of 64 keys built from LOGIT bits ---
    unsigned ub0 = __float_as_uint(l0);
    unsigned ub1 = __float_as_uint(l1);
    ub0 = (ub0 & 0x80000000u) ? ~ub0 : (ub0 | 0x80000000u);
    ub1 = (ub1 & 0x80000000u) ? ~ub1 : (ub1 | 0x80000000u);
    unsigned long long key0 =
        ((unsigned long long)ub0 << 6) | (unsigned long long)(63 - lane);
    unsigned long long key1 =
        ((unsigned long long)ub1 << 6) | (unsigned long long)(63 - (lane + 32));

    // descending bitonic sort; positions: key0 -> lane, key1 -> lane+32
#pragma unroll
    for (int k = 2; k <= 64; k <<= 1) {
#pragma unroll
        for (int j = k >> 1; j > 0; j >>= 1) {
            if (j == 32) {
                unsigned long long mx = key0 > key1 ? key0 : key1;
                unsigned long long mn = key0 > key1 ? key1 : key0;
                key0 = mx; key1 = mn;
            } else {
                bool wml0 = (k == 64) ? true : ((lane & k) == 0);
                bool wml1 = (k == 64) ? true : (((lane + 32) & k) == 0);
                bool lower = (lane & j) == 0;
                unsigned long long o0 = __shfl_xor_sync(FULL, key0, j);
                unsigned long long o1 = __shfl_xor_sync(FULL, key1, j);
                bool tm0 = (lower == wml0);
                bool tm1 = (lower == wml1);
                key0 = tm0 ? (key0 > o0 ? key0 : o0) : (key0 < o0 ? key0 : o0);
                key1 = tm1 ? (key1 > o1 ? key1 : o1) : (key1 < o1 ? key1 : o1);
            }
        }
    }

    int idx_sel = 63 - (int)(key0 & 63ull);
    float pa = __shfl_sync(FULL, p0, idx_sel & 31);
    float pb = __shfl_sync(FULL, p1, idx_sel & 31);
    float pv = (idx_sel < 32) ? pa : pb;

    if (lane < 8) {
        bool act = lane < dk;
        sel_w[(size_t)gwarp * 8 + lane] = act ? pv : 0.0f;
        sel_i[(size_t)gwarp * 8 + lane] = act ? (float)idx_sel : 0.0f;
    }
}

extern "C" void kernel_launch(void* const* d_in, const int* in_sizes, int n_in,
                              void* d_out, int out_size)
{
    const float* X  = (const float*)d_in[0];
    const float* Wr = (const float*)d_in[1];
    const float* br = (const float*)d_in[2];
    const float* W1 = (const float*)d_in[3];
    const float* b1 = (const float*)d_in[4];
    const float* W2 = (const float*)d_in[5];
    const float* b2 = (const float*)d_in[6];

    const int E  = in_sizes[2];                      // 64
    const int Hh = in_sizes[4];                      // 512
    const int H  = in_sizes[1] / E;                  // 1024
    const long long N = (long long)in_sizes[0] / H;  // 32768

    float* out    = (float*)d_out;
    float* sel_w  = out;
    float* sel_i  = out + N * 8;
    float* conf   = out + 2 * N * 8;
    float* logits = out + 2 * N * 8 + N;

    dim3 ggrid((unsigned)((N + BM - 1) / BM), (unsigned)(Hh / BN) + 1);
    es_gemm_fused_kernel<<<ggrid, THREADS>>>(X, Wr, br, W1, b1, logits,
                                             (int)N, H, E, Hh);

    int warps_per_block = 256 / 32;
    unsigned sel_blocks = (unsigned)((N + warps_per_block - 1) / warps_per_block);
    es_select_kernel<<<sel_blocks, 256>>>(logits, W2, b2,
                                          sel_w, sel_i, conf,
                                          (int)N, E, Hh);
}